// round 9
// baseline (speedup 1.0000x reference)
#include <cuda_runtime.h>
#include <math.h>

#define BB 64
#define TT 2048
#define HH 512
#define QQ 512
#define NCHUNK 16
#define CHUNK (TT / NCHUNK)   // 128 rows per chunk
#define QSPLIT 16
#define QSEG (QQ / QSPLIT)    // 32

// Scratch (allocation-free rule: __device__ globals)
__device__ __align__(16) float g_vp[QSPLIT * BB * HH];   // partial v (2 MB)
__device__ float g_pm[BB * NCHUNK];                      // per-chunk running max
__device__ float g_ps[BB * NCHUNK];                      // per-chunk exp-sum
__device__ __align__(16) float g_pctx[BB * NCHUNK * HH]; // per-chunk weighted ctx (2 MB)

__device__ __forceinline__ int detect_is64(const int* __restrict__ tgt_raw) {
    int odd_or = 0;
#pragma unroll
    for (int i = 1; i < 2 * BB; i += 2) odd_or |= tgt_raw[i];
    return odd_or == 0;
}
__device__ __forceinline__ int load_len(const int* __restrict__ tgt_raw, int b, int is64) {
    return (is64 ? tgt_raw[2 * b] : tgt_raw[b]) + 1;
}

__device__ __forceinline__ void cpa16(void* smem, const void* gmem) {
    unsigned s = (unsigned)__cvta_generic_to_shared(smem);
    asm volatile("cp.async.cg.shared.global [%0], [%1], 16;" :: "r"(s), "l"(gmem));
}

// ---------------------------------------------------------------------------
// Kernel 1: K-split partial matvec. grid (QSPLIT=16, 16) = 256 blocks,
// 256 threads (8 warps). tid&127 = h-float4 slot; tid>>7 selects 2 of the 4
// batches. W staged via classic multistage cp.async pipeline (NBUF=4, 4-row
// stages, 32 KB) with per-stage __syncthreads (halves share staged data).
// ---------------------------------------------------------------------------
#define K1_BGRP   4
#define K1_ROWS   4
#define K1_NBUF   4
#define K1_STAGES (QSEG / K1_ROWS)   // 8

__global__ __launch_bounds__(256) void k1_proj(const float* __restrict__ query,
                                               const float* __restrict__ W) {
    const int qz = blockIdx.x;
    const int b0 = blockIdx.y * K1_BGRP;
    const int tid = threadIdx.x;
    const int h4 = tid & 127;
    const int bh = tid >> 7;              // 0: batches b0,b0+1  1: b0+2,b0+3

    __shared__ float sq[K1_BGRP][QSEG];                         // 0.5 KB
    __shared__ __align__(16) float4 sw[K1_NBUF][K1_ROWS * 128]; // 32 KB

    if (tid < K1_BGRP * QSEG)
        sq[tid >> 5][tid & 31] = query[(b0 + (tid >> 5)) * QQ + qz * QSEG + (tid & 31)];

    const float4* Wg = (const float4*)W + (size_t)qz * QSEG * (HH / 4);

    // prefetch stages 0..NBUF-2 (each stage = 512 float4; 2 cpa per thread)
#pragma unroll
    for (int s = 0; s < K1_NBUF - 1; s++) {
        cpa16(&sw[s][tid],       Wg + s * 512 + tid);
        cpa16(&sw[s][tid + 256], Wg + s * 512 + tid + 256);
        asm volatile("cp.async.commit_group;");
    }
    __syncthreads();                      // sq visible

    float4 a0 = make_float4(0.f, 0.f, 0.f, 0.f), a1 = a0;
    const int bq0 = 2 * bh, bq1 = 2 * bh + 1;

#pragma unroll
    for (int s = 0; s < K1_STAGES; s++) {
        asm volatile("cp.async.wait_group %0;" :: "n"(K1_NBUF - 2));
        __syncthreads();                  // staged stage-s data visible to all
        const int buf = s & (K1_NBUF - 1);
#pragma unroll
        for (int r = 0; r < K1_ROWS; r++) {
            const float4 w = sw[buf][r * 128 + h4];
            const int qi = s * K1_ROWS + r;
            const float q0 = sq[bq0][qi], q1 = sq[bq1][qi];
            a0.x = fmaf(w.x, q0, a0.x); a0.y = fmaf(w.y, q0, a0.y);
            a0.z = fmaf(w.z, q0, a0.z); a0.w = fmaf(w.w, q0, a0.w);
            a1.x = fmaf(w.x, q1, a1.x); a1.y = fmaf(w.y, q1, a1.y);
            a1.z = fmaf(w.z, q1, a1.z); a1.w = fmaf(w.w, q1, a1.w);
        }
        // refill buf (s+NBUF-1)&3 with stage s+NBUF-1 (safe: all threads are
        // past stage s-1 consumption thanks to the barrier above)
        const int sn = s + K1_NBUF - 1;
        if (sn < K1_STAGES) {
            const int nb = sn & (K1_NBUF - 1);
            cpa16(&sw[nb][tid],       Wg + sn * 512 + tid);
            cpa16(&sw[nb][tid + 256], Wg + sn * 512 + tid + 256);
        }
        asm volatile("cp.async.commit_group;");
    }

    float4* vp = (float4*)g_vp + (size_t)qz * BB * (HH / 4);
    vp[(b0 + bq0) * (HH / 4) + h4] = a0;
    vp[(b0 + bq1) * (HH / 4) + h4] = a1;
}

// ---------------------------------------------------------------------------
// Kernel 2: flash pass, per-warp barrier-free cp.async pipeline (NSTAGE=3).
// (Frozen at the R8-passing version; only the v-reduce loops over 16 partials.)
// ---------------------------------------------------------------------------
#define K2_NSTAGE 3

__device__ __forceinline__ float dot4(float4 a, float4 b) {
    return a.x * b.x + a.y * b.y + a.z * b.z + a.w * b.w;
}

#define PROCESS_ROW(E0, E1, E2, E3)                                              \
    {                                                                            \
        float d = dot4(E0, va) + dot4(E1, vb) + dot4(E2, vc) + dot4(E3, vd);     \
        d += __shfl_xor_sync(0xFFFFFFFFu, d, 16);                                \
        d += __shfl_xor_sync(0xFFFFFFFFu, d, 8);                                 \
        d += __shfl_xor_sync(0xFFFFFFFFu, d, 4);                                 \
        d += __shfl_xor_sync(0xFFFFFFFFu, d, 2);                                 \
        d += __shfl_xor_sync(0xFFFFFFFFu, d, 1);                                 \
        if (d > m) {                                                             \
            const float alpha = __expf(m - d);                                   \
            m = d;                                                               \
            ssum = ssum * alpha + 1.f;                                           \
            c0.x = c0.x * alpha + E0.x; c0.y = c0.y * alpha + E0.y;              \
            c0.z = c0.z * alpha + E0.z; c0.w = c0.w * alpha + E0.w;              \
            c1.x = c1.x * alpha + E1.x; c1.y = c1.y * alpha + E1.y;              \
            c1.z = c1.z * alpha + E1.z; c1.w = c1.w * alpha + E1.w;              \
            c2.x = c2.x * alpha + E2.x; c2.y = c2.y * alpha + E2.y;              \
            c2.z = c2.z * alpha + E2.z; c2.w = c2.w * alpha + E2.w;              \
            c3.x = c3.x * alpha + E3.x; c3.y = c3.y * alpha + E3.y;              \
            c3.z = c3.z * alpha + E3.z; c3.w = c3.w * alpha + E3.w;              \
        } else {                                                                 \
            const float p = __expf(d - m);                                       \
            ssum += p;                                                           \
            c0.x = fmaf(p, E0.x, c0.x); c0.y = fmaf(p, E0.y, c0.y);              \
            c0.z = fmaf(p, E0.z, c0.z); c0.w = fmaf(p, E0.w, c0.w);              \
            c1.x = fmaf(p, E1.x, c1.x); c1.y = fmaf(p, E1.y, c1.y);              \
            c1.z = fmaf(p, E1.z, c1.z); c1.w = fmaf(p, E1.w, c1.w);              \
            c2.x = fmaf(p, E2.x, c2.x); c2.y = fmaf(p, E2.y, c2.y);              \
            c2.z = fmaf(p, E2.z, c2.z); c2.w = fmaf(p, E2.w, c2.w);              \
            c3.x = fmaf(p, E3.x, c3.x); c3.y = fmaf(p, E3.y, c3.y);              \
            c3.z = fmaf(p, E3.z, c3.z); c3.w = fmaf(p, E3.w, c3.w);              \
        }                                                                        \
    }

__global__ __launch_bounds__(256, 4) void k2_flash(const float* __restrict__ enc,
                                                   const int* __restrict__ tgt_raw) {
    __shared__ __align__(16) float4 sbuf[K2_NSTAGE][8 * 128];   // 48 KB (static max)

    const int b = blockIdx.y;
    const int c = blockIdx.x;
    const int tid = threadIdx.x, w = tid >> 5, lane = tid & 31;

    // dtype flag via sbuf scratch (free until prefetch)
    int* flag = (int*)&sbuf[0][0];
    if (tid == 0) *flag = detect_is64(tgt_raw);
    __syncthreads();
    const int is64 = *flag;
    __syncthreads();                             // everyone read before overwrite

    const int L = load_len(tgt_raw, b, is64);    // valid rows: t in [0, L)
    const int t0 = c * CHUNK;
    if (t0 >= L) {                               // entirely masked chunk
        if (tid == 0) g_ps[b * NCHUNK + c] = 0.f;
        return;
    }
    const int tend = min(t0 + CHUNK, L);
    const int total = (tend - t0 + 7) >> 3;      // stages for this block

    // v[b] = sum of QSPLIT partials (L2-hit loads)
    float4 va = make_float4(0.f, 0.f, 0.f, 0.f), vb = va, vc = va, vd = va;
#pragma unroll
    for (int z = 0; z < QSPLIT; z++) {
        const float4* vp = (const float4*)g_vp + ((size_t)z * BB + b) * (HH / 4);
        const float4 p0 = vp[lane], p1 = vp[lane + 32], p2 = vp[lane + 64], p3 = vp[lane + 96];
        va.x += p0.x; va.y += p0.y; va.z += p0.z; va.w += p0.w;
        vb.x += p1.x; vb.y += p1.y; vb.z += p1.z; vb.w += p1.w;
        vc.x += p2.x; vc.y += p2.y; vc.z += p2.z; vc.w += p2.w;
        vd.x += p3.x; vd.y += p3.y; vd.z += p3.z; vd.w += p3.w;
    }

    const float4* ebase = (const float4*)enc + (size_t)b * TT * (HH / 4);

    // prefetch stages 0..2 (row t0 + st*8 + w; each thread stages what it reads)
#pragma unroll
    for (int st = 0; st < K2_NSTAGE; st++) {
        const int row = t0 + st * 8 + w;
        if (row < tend) {
            const float4* src = ebase + (size_t)row * 128;
#pragma unroll
            for (int k = 0; k < 4; k++)
                cpa16(&sbuf[st][w * 128 + lane + k * 32], src + lane + k * 32);
        }
        asm volatile("cp.async.commit_group;");
    }

    float m = -INFINITY, ssum = 0.f;
    float4 c0 = make_float4(0.f, 0.f, 0.f, 0.f), c1 = c0, c2 = c0, c3 = c0;

    for (int st = 0; st < total; st++) {
        asm volatile("cp.async.wait_group %0;" :: "n"(K2_NSTAGE - 1));
        const int buf = st % K2_NSTAGE;
        const int row = t0 + st * 8 + w;
        if (row < tend) {
            const float4 e0 = sbuf[buf][w * 128 + lane];
            const float4 e1 = sbuf[buf][w * 128 + lane + 32];
            const float4 e2 = sbuf[buf][w * 128 + lane + 64];
            const float4 e3 = sbuf[buf][w * 128 + lane + 96];
            PROCESS_ROW(e0, e1, e2, e3);
        }
        // refill this buffer with stage st+NSTAGE (empty commit past the end)
        const int row2 = t0 + (st + K2_NSTAGE) * 8 + w;
        if (row2 < tend) {
            const float4* src = ebase + (size_t)row2 * 128;
#pragma unroll
            for (int k = 0; k < 4; k++)
                cpa16(&sbuf[buf][w * 128 + lane + k * 32], src + lane + k * 32);
        }
        asm volatile("cp.async.commit_group;");
    }
    asm volatile("cp.async.wait_group 0;");
    __syncthreads();                              // pipeline drained; reuse sbuf

    // ---- combine 8 warps: overlay sctx/sM/sS on sbuf ----
    float* sctx = (float*)sbuf;                   // [8][512] = 16 KB
    float* sMv  = (float*)sbuf + 8 * HH;          // 8 floats (start of sbuf[1])
    float* sSv  = sMv + 8;

    float4* sc4 = (float4*)(sctx + w * HH);
    sc4[lane] = c0; sc4[lane + 32] = c1; sc4[lane + 64] = c2; sc4[lane + 96] = c3;
    if (lane == 0) { sMv[w] = m; sSv[w] = ssum; }
    __syncthreads();

    float M = -INFINITY;
#pragma unroll
    for (int i = 0; i < 8; i++) if (sSv[i] > 0.f) M = fmaxf(M, sMv[i]);
    float S = 0.f, f[8];
#pragma unroll
    for (int i = 0; i < 8; i++) {
        f[i] = (sSv[i] > 0.f) ? __expf(sMv[i] - M) : 0.f;
        S += sSv[i] * f[i];
    }
    const int base = (b * NCHUNK + c) * HH;
    for (int h = tid; h < HH; h += 256) {
        float a = 0.f;
#pragma unroll
        for (int i = 0; i < 8; i++) a = fmaf(sctx[i * HH + h], f[i], a);
        g_pctx[base + h] = a;
    }
    if (tid == 0) { g_pm[b * NCHUNK + c] = M; g_ps[b * NCHUNK + c] = S; }
}

// ---------------------------------------------------------------------------
// Kernel 3: combine the NCHUNK split-softmax partials per batch.
// ---------------------------------------------------------------------------
__global__ void k3_combine(float* __restrict__ out) {
    const int b = blockIdx.x, h = threadIdx.x;   // 512 threads
    float M = -INFINITY;
#pragma unroll
    for (int c = 0; c < NCHUNK; c++) {
        const float s = g_ps[b * NCHUNK + c];
        if (s > 0.f) M = fmaxf(M, g_pm[b * NCHUNK + c]);
    }
    float S = 0.f, acc = 0.f;
#pragma unroll
    for (int c = 0; c < NCHUNK; c++) {
        const float s = g_ps[b * NCHUNK + c];
        if (s > 0.f) {
            const float fct = __expf(g_pm[b * NCHUNK + c] - M);
            S += s * fct;
            acc = fmaf(g_pctx[(b * NCHUNK + c) * HH + h], fct, acc);
        }
    }
    out[b * HH + h] = acc / S;
}

// ---------------------------------------------------------------------------
extern "C" void kernel_launch(void* const* d_in, const int* in_sizes, int n_in,
                              void* d_out, int out_size) {
    const float* query = nullptr;
    const float* enc   = nullptr;
    const float* W     = nullptr;
    const int*   tgt   = nullptr;   // dtype (i32 vs i64) detected on device
    for (int i = 0; i < n_in; i++) {
        switch (in_sizes[i]) {
            case BB * QQ:               query = (const float*)d_in[i]; break;
            case BB * TT * HH:          enc   = (const float*)d_in[i]; break;
            case QQ * HH:               W     = (const float*)d_in[i]; break;
            case BB:                    tgt   = (const int*)d_in[i]; break;
            default: break;             // bias (512) unused: softmax-shift invariant
        }
    }

    k1_proj<<<dim3(QSPLIT, BB / K1_BGRP), 256>>>(query, W);
    k2_flash<<<dim3(NCHUNK, BB), 256>>>(enc, tgt);
    k3_combine<<<BB, HH>>>((float*)d_out);
}

// round 10
// speedup vs baseline: 1.0373x; 1.0373x over previous
#include <cuda_runtime.h>
#include <math.h>

#define BB 64
#define TT 2048
#define HH 512
#define QQ 512
#define NCHUNK 16
#define CHUNK (TT / NCHUNK)   // 128 rows per chunk
#define QSPLIT 16
#define QSEG (QQ / QSPLIT)    // 32

// Scratch (allocation-free rule: __device__ globals)
__device__ __align__(16) float g_vp[QSPLIT * BB * HH];   // partial v (2 MB)
__device__ float g_pm[BB * NCHUNK];                      // per-chunk running max
__device__ float g_ps[BB * NCHUNK];                      // per-chunk exp-sum
__device__ __align__(16) float g_pctx[BB * NCHUNK * HH]; // per-chunk weighted ctx (2 MB)

__device__ __forceinline__ int detect_is64(const int* __restrict__ tgt_raw) {
    int odd_or = 0;
#pragma unroll
    for (int i = 1; i < 2 * BB; i += 2) odd_or |= tgt_raw[i];
    return odd_or == 0;
}
__device__ __forceinline__ int load_len(const int* __restrict__ tgt_raw, int b, int is64) {
    return (is64 ? tgt_raw[2 * b] : tgt_raw[b]) + 1;
}

__device__ __forceinline__ void cpa16(void* smem, const void* gmem) {
    unsigned s = (unsigned)__cvta_generic_to_shared(smem);
    asm volatile("cp.async.cg.shared.global [%0], [%1], 16;" :: "r"(s), "l"(gmem));
}

// ---------------------------------------------------------------------------
// Kernel 1: K-split partial matvec (frozen R9 version: 6.6 us).
// grid (QSPLIT=16, 16) = 256 blocks, 256 threads (8 warps).
// ---------------------------------------------------------------------------
#define K1_BGRP   4
#define K1_ROWS   4
#define K1_NBUF   4
#define K1_STAGES (QSEG / K1_ROWS)   // 8

__global__ __launch_bounds__(256) void k1_proj(const float* __restrict__ query,
                                               const float* __restrict__ W) {
    const int qz = blockIdx.x;
    const int b0 = blockIdx.y * K1_BGRP;
    const int tid = threadIdx.x;
    const int h4 = tid & 127;
    const int bh = tid >> 7;              // 0: batches b0,b0+1  1: b0+2,b0+3

    __shared__ float sq[K1_BGRP][QSEG];                         // 0.5 KB
    __shared__ __align__(16) float4 sw[K1_NBUF][K1_ROWS * 128]; // 32 KB

    if (tid < K1_BGRP * QSEG)
        sq[tid >> 5][tid & 31] = query[(b0 + (tid >> 5)) * QQ + qz * QSEG + (tid & 31)];

    const float4* Wg = (const float4*)W + (size_t)qz * QSEG * (HH / 4);

#pragma unroll
    for (int s = 0; s < K1_NBUF - 1; s++) {
        cpa16(&sw[s][tid],       Wg + s * 512 + tid);
        cpa16(&sw[s][tid + 256], Wg + s * 512 + tid + 256);
        asm volatile("cp.async.commit_group;");
    }
    __syncthreads();                      // sq visible

    float4 a0 = make_float4(0.f, 0.f, 0.f, 0.f), a1 = a0;
    const int bq0 = 2 * bh, bq1 = 2 * bh + 1;

#pragma unroll
    for (int s = 0; s < K1_STAGES; s++) {
        asm volatile("cp.async.wait_group %0;" :: "n"(K1_NBUF - 2));
        __syncthreads();                  // staged stage-s data visible to all
        const int buf = s & (K1_NBUF - 1);
#pragma unroll
        for (int r = 0; r < K1_ROWS; r++) {
            const float4 w = sw[buf][r * 128 + h4];
            const int qi = s * K1_ROWS + r;
            const float q0 = sq[bq0][qi], q1 = sq[bq1][qi];
            a0.x = fmaf(w.x, q0, a0.x); a0.y = fmaf(w.y, q0, a0.y);
            a0.z = fmaf(w.z, q0, a0.z); a0.w = fmaf(w.w, q0, a0.w);
            a1.x = fmaf(w.x, q1, a1.x); a1.y = fmaf(w.y, q1, a1.y);
            a1.z = fmaf(w.z, q1, a1.z); a1.w = fmaf(w.w, q1, a1.w);
        }
        const int sn = s + K1_NBUF - 1;
        if (sn < K1_STAGES) {
            const int nb = sn & (K1_NBUF - 1);
            cpa16(&sw[nb][tid],       Wg + sn * 512 + tid);
            cpa16(&sw[nb][tid + 256], Wg + sn * 512 + tid + 256);
        }
        asm volatile("cp.async.commit_group;");
    }

    float4* vp = (float4*)g_vp + (size_t)qz * BB * (HH / 4);
    vp[(b0 + bq0) * (HH / 4) + h4] = a0;
    vp[(b0 + bq1) * (HH / 4) + h4] = a1;
}

// ---------------------------------------------------------------------------
// Kernel 2: flash pass, per-warp barrier-free cp.async pipeline (NSTAGE=3).
// v-reduce is COOPERATIVE: warp w sums partials z=2w,2w+1 into sbuf scratch,
// then every thread sums the 8 warp-sums from smem (8 global loads/thread,
// was 64).
// ---------------------------------------------------------------------------
#define K2_NSTAGE 3

__device__ __forceinline__ float dot4(float4 a, float4 b) {
    return a.x * b.x + a.y * b.y + a.z * b.z + a.w * b.w;
}

#define PROCESS_ROW(E0, E1, E2, E3)                                              \
    {                                                                            \
        float d = dot4(E0, va) + dot4(E1, vb) + dot4(E2, vc) + dot4(E3, vd);     \
        d += __shfl_xor_sync(0xFFFFFFFFu, d, 16);                                \
        d += __shfl_xor_sync(0xFFFFFFFFu, d, 8);                                 \
        d += __shfl_xor_sync(0xFFFFFFFFu, d, 4);                                 \
        d += __shfl_xor_sync(0xFFFFFFFFu, d, 2);                                 \
        d += __shfl_xor_sync(0xFFFFFFFFu, d, 1);                                 \
        if (d > m) {                                                             \
            const float alpha = __expf(m - d);                                   \
            m = d;                                                               \
            ssum = ssum * alpha + 1.f;                                           \
            c0.x = c0.x * alpha + E0.x; c0.y = c0.y * alpha + E0.y;              \
            c0.z = c0.z * alpha + E0.z; c0.w = c0.w * alpha + E0.w;              \
            c1.x = c1.x * alpha + E1.x; c1.y = c1.y * alpha + E1.y;              \
            c1.z = c1.z * alpha + E1.z; c1.w = c1.w * alpha + E1.w;              \
            c2.x = c2.x * alpha + E2.x; c2.y = c2.y * alpha + E2.y;              \
            c2.z = c2.z * alpha + E2.z; c2.w = c2.w * alpha + E2.w;              \
            c3.x = c3.x * alpha + E3.x; c3.y = c3.y * alpha + E3.y;              \
            c3.z = c3.z * alpha + E3.z; c3.w = c3.w * alpha + E3.w;              \
        } else {                                                                 \
            const float p = __expf(d - m);                                       \
            ssum += p;                                                           \
            c0.x = fmaf(p, E0.x, c0.x); c0.y = fmaf(p, E0.y, c0.y);              \
            c0.z = fmaf(p, E0.z, c0.z); c0.w = fmaf(p, E0.w, c0.w);              \
            c1.x = fmaf(p, E1.x, c1.x); c1.y = fmaf(p, E1.y, c1.y);              \
            c1.z = fmaf(p, E1.z, c1.z); c1.w = fmaf(p, E1.w, c1.w);              \
            c2.x = fmaf(p, E2.x, c2.x); c2.y = fmaf(p, E2.y, c2.y);              \
            c2.z = fmaf(p, E2.z, c2.z); c2.w = fmaf(p, E2.w, c2.w);              \
            c3.x = fmaf(p, E3.x, c3.x); c3.y = fmaf(p, E3.y, c3.y);              \
            c3.z = fmaf(p, E3.z, c3.z); c3.w = fmaf(p, E3.w, c3.w);              \
        }                                                                        \
    }

__global__ __launch_bounds__(256, 4) void k2_flash(const float* __restrict__ enc,
                                                   const int* __restrict__ tgt_raw) {
    __shared__ __align__(16) float4 sbuf[K2_NSTAGE][8 * 128];   // 48 KB (static max)

    const int b = blockIdx.y;
    const int c = blockIdx.x;
    const int tid = threadIdx.x, w = tid >> 5, lane = tid & 31;

    // dtype flag via sbuf scratch (free until prefetch)
    int* flag = (int*)&sbuf[0][0];
    if (tid == 0) *flag = detect_is64(tgt_raw);
    __syncthreads();
    const int is64 = *flag;
    __syncthreads();                             // everyone read before overwrite

    const int L = load_len(tgt_raw, b, is64);    // valid rows: t in [0, L)
    const int t0 = c * CHUNK;
    if (t0 >= L) {                               // entirely masked chunk
        if (tid == 0) g_ps[b * NCHUNK + c] = 0.f;
        return;
    }
    const int tend = min(t0 + CHUNK, L);
    const int total = (tend - t0 + 7) >> 3;      // stages for this block

    // ---- cooperative v-reduce: warp w covers partials z=2w, 2w+1 ----
    float4 va = make_float4(0.f, 0.f, 0.f, 0.f), vb = va, vc = va, vd = va;
#pragma unroll
    for (int zz = 0; zz < 2; zz++) {
        const int z = 2 * w + zz;
        const float4* vp = (const float4*)g_vp + ((size_t)z * BB + b) * (HH / 4);
        const float4 p0 = vp[lane], p1 = vp[lane + 32], p2 = vp[lane + 64], p3 = vp[lane + 96];
        va.x += p0.x; va.y += p0.y; va.z += p0.z; va.w += p0.w;
        vb.x += p1.x; vb.y += p1.y; vb.z += p1.z; vb.w += p1.w;
        vc.x += p2.x; vc.y += p2.y; vc.z += p2.z; vc.w += p2.w;
        vd.x += p3.x; vd.y += p3.y; vd.z += p3.z; vd.w += p3.w;
    }
    {
        float4* sred = (float4*)sbuf;            // [8][128] float4 = 16 KB
        sred[w * 128 + lane] = va;
        sred[w * 128 + lane + 32] = vb;
        sred[w * 128 + lane + 64] = vc;
        sred[w * 128 + lane + 96] = vd;
        __syncthreads();
        va = vb = vc = vd = make_float4(0.f, 0.f, 0.f, 0.f);
#pragma unroll
        for (int i = 0; i < 8; i++) {
            const float4 p0 = sred[i * 128 + lane];
            const float4 p1 = sred[i * 128 + lane + 32];
            const float4 p2 = sred[i * 128 + lane + 64];
            const float4 p3 = sred[i * 128 + lane + 96];
            va.x += p0.x; va.y += p0.y; va.z += p0.z; va.w += p0.w;
            vb.x += p1.x; vb.y += p1.y; vb.z += p1.z; vb.w += p1.w;
            vc.x += p2.x; vc.y += p2.y; vc.z += p2.z; vc.w += p2.w;
            vd.x += p3.x; vd.y += p3.y; vd.z += p3.z; vd.w += p3.w;
        }
        __syncthreads();                         // sred dead before prefetch
    }

    const float4* ebase = (const float4*)enc + (size_t)b * TT * (HH / 4);

    // prefetch stages 0..2 (row t0 + st*8 + w; each thread stages what it reads)
#pragma unroll
    for (int st = 0; st < K2_NSTAGE; st++) {
        const int row = t0 + st * 8 + w;
        if (row < tend) {
            const float4* src = ebase + (size_t)row * 128;
#pragma unroll
            for (int k = 0; k < 4; k++)
                cpa16(&sbuf[st][w * 128 + lane + k * 32], src + lane + k * 32);
        }
        asm volatile("cp.async.commit_group;");
    }

    float m = -INFINITY, ssum = 0.f;
    float4 c0 = make_float4(0.f, 0.f, 0.f, 0.f), c1 = c0, c2 = c0, c3 = c0;

    for (int st = 0; st < total; st++) {
        asm volatile("cp.async.wait_group %0;" :: "n"(K2_NSTAGE - 1));
        const int buf = st % K2_NSTAGE;
        const int row = t0 + st * 8 + w;
        if (row < tend) {
            const float4 e0 = sbuf[buf][w * 128 + lane];
            const float4 e1 = sbuf[buf][w * 128 + lane + 32];
            const float4 e2 = sbuf[buf][w * 128 + lane + 64];
            const float4 e3 = sbuf[buf][w * 128 + lane + 96];
            PROCESS_ROW(e0, e1, e2, e3);
        }
        const int row2 = t0 + (st + K2_NSTAGE) * 8 + w;
        if (row2 < tend) {
            const float4* src = ebase + (size_t)row2 * 128;
#pragma unroll
            for (int k = 0; k < 4; k++)
                cpa16(&sbuf[buf][w * 128 + lane + k * 32], src + lane + k * 32);
        }
        asm volatile("cp.async.commit_group;");
    }
    asm volatile("cp.async.wait_group 0;");
    __syncthreads();                              // pipeline drained; reuse sbuf

    // ---- combine 8 warps: overlay sctx/sM/sS on sbuf ----
    float* sctx = (float*)sbuf;                   // [8][512] = 16 KB
    float* sMv  = (float*)sbuf + 8 * HH;          // 8 floats (start of sbuf[1])
    float* sSv  = sMv + 8;

    float4* sc4 = (float4*)(sctx + w * HH);
    sc4[lane] = c0; sc4[lane + 32] = c1; sc4[lane + 64] = c2; sc4[lane + 96] = c3;
    if (lane == 0) { sMv[w] = m; sSv[w] = ssum; }
    __syncthreads();

    float M = -INFINITY;
#pragma unroll
    for (int i = 0; i < 8; i++) if (sSv[i] > 0.f) M = fmaxf(M, sMv[i]);
    float S = 0.f, f[8];
#pragma unroll
    for (int i = 0; i < 8; i++) {
        f[i] = (sSv[i] > 0.f) ? __expf(sMv[i] - M) : 0.f;
        S += sSv[i] * f[i];
    }
    const int base = (b * NCHUNK + c) * HH;
    for (int h = tid; h < HH; h += 256) {
        float a = 0.f;
#pragma unroll
        for (int i = 0; i < 8; i++) a = fmaf(sctx[i * HH + h], f[i], a);
        g_pctx[base + h] = a;
    }
    if (tid == 0) { g_pm[b * NCHUNK + c] = M; g_ps[b * NCHUNK + c] = S; }
}

// ---------------------------------------------------------------------------
// Kernel 3: combine the NCHUNK split-softmax partials per batch.
// ---------------------------------------------------------------------------
__global__ void k3_combine(float* __restrict__ out) {
    const int b = blockIdx.x, h = threadIdx.x;   // 512 threads
    float M = -INFINITY;
#pragma unroll
    for (int c = 0; c < NCHUNK; c++) {
        const float s = g_ps[b * NCHUNK + c];
        if (s > 0.f) M = fmaxf(M, g_pm[b * NCHUNK + c]);
    }
    float S = 0.f, acc = 0.f;
#pragma unroll
    for (int c = 0; c < NCHUNK; c++) {
        const float s = g_ps[b * NCHUNK + c];
        if (s > 0.f) {
            const float fct = __expf(g_pm[b * NCHUNK + c] - M);
            S += s * fct;
            acc = fmaf(g_pctx[(b * NCHUNK + c) * HH + h], fct, acc);
        }
    }
    out[b * HH + h] = acc / S;
}

// ---------------------------------------------------------------------------
extern "C" void kernel_launch(void* const* d_in, const int* in_sizes, int n_in,
                              void* d_out, int out_size) {
    const float* query = nullptr;
    const float* enc   = nullptr;
    const float* W     = nullptr;
    const int*   tgt   = nullptr;   // dtype (i32 vs i64) detected on device
    for (int i = 0; i < n_in; i++) {
        switch (in_sizes[i]) {
            case BB * QQ:               query = (const float*)d_in[i]; break;
            case BB * TT * HH:          enc   = (const float*)d_in[i]; break;
            case QQ * HH:               W     = (const float*)d_in[i]; break;
            case BB:                    tgt   = (const int*)d_in[i]; break;
            default: break;             // bias (512) unused: softmax-shift invariant
        }
    }

    k1_proj<<<dim3(QSPLIT, BB / K1_BGRP), 256>>>(query, W);
    k2_flash<<<dim3(NCHUNK, BB), 256>>>(enc, tgt);
    k3_combine<<<BB, HH>>>((float*)d_out);
}

// round 11
// speedup vs baseline: 1.0571x; 1.0190x over previous
#include <cuda_runtime.h>
#include <math.h>

#define BB 64
#define TT 2048
#define HH 512
#define QQ 512
#define NCHUNK 16
#define CHUNK (TT / NCHUNK)   // 128 rows per chunk
#define QSPLIT 16
#define QSEG (QQ / QSPLIT)    // 32

// Scratch (allocation-free rule: __device__ globals)
__device__ __align__(16) float g_vp[QSPLIT * BB * HH];   // partial v (2 MB)
__device__ __align__(16) float g_v[BB * HH];             // final v (128 KB)
__device__ int   g_len[BB];                              // valid length per batch
__device__ float g_pm[BB * NCHUNK];                      // per-chunk running max
__device__ float g_ps[BB * NCHUNK];                      // per-chunk exp-sum
__device__ __align__(16) float g_pctx[BB * NCHUNK * HH]; // per-chunk weighted ctx (2 MB)

__device__ __forceinline__ void cpa16(void* smem, const void* gmem) {
    unsigned s = (unsigned)__cvta_generic_to_shared(smem);
    asm volatile("cp.async.cg.shared.global [%0], [%1], 16;" :: "r"(s), "l"(gmem));
}

// ---------------------------------------------------------------------------
// Kernel 1: K-split partial matvec (frozen: 6.6 us).
// grid (QSPLIT=16, 16) = 256 blocks, 256 threads (8 warps).
// ---------------------------------------------------------------------------
#define K1_BGRP   4
#define K1_ROWS   4
#define K1_NBUF   4
#define K1_STAGES (QSEG / K1_ROWS)   // 8

__global__ __launch_bounds__(256) void k1_proj(const float* __restrict__ query,
                                               const float* __restrict__ W) {
    const int qz = blockIdx.x;
    const int b0 = blockIdx.y * K1_BGRP;
    const int tid = threadIdx.x;
    const int h4 = tid & 127;
    const int bh = tid >> 7;              // 0: batches b0,b0+1  1: b0+2,b0+3

    __shared__ float sq[K1_BGRP][QSEG];                         // 0.5 KB
    __shared__ __align__(16) float4 sw[K1_NBUF][K1_ROWS * 128]; // 32 KB

    if (tid < K1_BGRP * QSEG)
        sq[tid >> 5][tid & 31] = query[(b0 + (tid >> 5)) * QQ + qz * QSEG + (tid & 31)];

    const float4* Wg = (const float4*)W + (size_t)qz * QSEG * (HH / 4);

#pragma unroll
    for (int s = 0; s < K1_NBUF - 1; s++) {
        cpa16(&sw[s][tid],       Wg + s * 512 + tid);
        cpa16(&sw[s][tid + 256], Wg + s * 512 + tid + 256);
        asm volatile("cp.async.commit_group;");
    }
    __syncthreads();                      // sq visible

    float4 a0 = make_float4(0.f, 0.f, 0.f, 0.f), a1 = a0;
    const int bq0 = 2 * bh, bq1 = 2 * bh + 1;

#pragma unroll
    for (int s = 0; s < K1_STAGES; s++) {
        asm volatile("cp.async.wait_group %0;" :: "n"(K1_NBUF - 2));
        __syncthreads();                  // staged stage-s data visible to all
        const int buf = s & (K1_NBUF - 1);
#pragma unroll
        for (int r = 0; r < K1_ROWS; r++) {
            const float4 w = sw[buf][r * 128 + h4];
            const int qi = s * K1_ROWS + r;
            const float q0 = sq[bq0][qi], q1 = sq[bq1][qi];
            a0.x = fmaf(w.x, q0, a0.x); a0.y = fmaf(w.y, q0, a0.y);
            a0.z = fmaf(w.z, q0, a0.z); a0.w = fmaf(w.w, q0, a0.w);
            a1.x = fmaf(w.x, q1, a1.x); a1.y = fmaf(w.y, q1, a1.y);
            a1.z = fmaf(w.z, q1, a1.z); a1.w = fmaf(w.w, q1, a1.w);
        }
        const int sn = s + K1_NBUF - 1;
        if (sn < K1_STAGES) {
            const int nb = sn & (K1_NBUF - 1);
            cpa16(&sw[nb][tid],       Wg + sn * 512 + tid);
            cpa16(&sw[nb][tid + 256], Wg + sn * 512 + tid + 256);
        }
        asm volatile("cp.async.commit_group;");
    }

    float4* vp = (float4*)g_vp + (size_t)qz * BB * (HH / 4);
    vp[(b0 + bq0) * (HH / 4) + h4] = a0;
    vp[(b0 + bq1) * (HH / 4) + h4] = a1;
}

// ---------------------------------------------------------------------------
// Kernel 1b: hoisted per-batch preamble. grid (BB=64), 128 threads.
// Reduces the 16 v-partials to g_v[b] (16 independent L2 loads per thread)
// and computes g_len[b] once (incl. int64/int32 detection).
// ---------------------------------------------------------------------------
__global__ __launch_bounds__(128) void k1b_reduce(const int* __restrict__ tgt_raw) {
    const int b = blockIdx.x;
    const int tid = threadIdx.x;          // h-float4 slot

    float4 a = make_float4(0.f, 0.f, 0.f, 0.f);
#pragma unroll
    for (int z = 0; z < QSPLIT; z++) {
        const float4 p = ((const float4*)g_vp)[((size_t)z * BB + b) * (HH / 4) + tid];
        a.x += p.x; a.y += p.y; a.z += p.z; a.w += p.w;
    }
    ((float4*)g_v)[b * (HH / 4) + tid] = a;

    if (tid == 0) {
        int odd_or = 0;
#pragma unroll
        for (int i = 1; i < 2 * BB; i += 2) odd_or |= tgt_raw[i];
        const int is64 = (odd_or == 0);
        g_len[b] = (is64 ? tgt_raw[2 * b] : tgt_raw[b]) + 1;
    }
}

// ---------------------------------------------------------------------------
// Kernel 2: flash pass, per-warp barrier-free cp.async pipeline (NSTAGE=3).
// Preamble is now just: 1 load of g_len[b] + 4 float4 loads of g_v.
// ---------------------------------------------------------------------------
#define K2_NSTAGE 3

__device__ __forceinline__ float dot4(float4 a, float4 b) {
    return a.x * b.x + a.y * b.y + a.z * b.z + a.w * b.w;
}

#define PROCESS_ROW(E0, E1, E2, E3)                                              \
    {                                                                            \
        float d = dot4(E0, va) + dot4(E1, vb) + dot4(E2, vc) + dot4(E3, vd);     \
        d += __shfl_xor_sync(0xFFFFFFFFu, d, 16);                                \
        d += __shfl_xor_sync(0xFFFFFFFFu, d, 8);                                 \
        d += __shfl_xor_sync(0xFFFFFFFFu, d, 4);                                 \
        d += __shfl_xor_sync(0xFFFFFFFFu, d, 2);                                 \
        d += __shfl_xor_sync(0xFFFFFFFFu, d, 1);                                 \
        if (d > m) {                                                             \
            const float alpha = __expf(m - d);                                   \
            m = d;                                                               \
            ssum = ssum * alpha + 1.f;                                           \
            c0.x = c0.x * alpha + E0.x; c0.y = c0.y * alpha + E0.y;              \
            c0.z = c0.z * alpha + E0.z; c0.w = c0.w * alpha + E0.w;              \
            c1.x = c1.x * alpha + E1.x; c1.y = c1.y * alpha + E1.y;              \
            c1.z = c1.z * alpha + E1.z; c1.w = c1.w * alpha + E1.w;              \
            c2.x = c2.x * alpha + E2.x; c2.y = c2.y * alpha + E2.y;              \
            c2.z = c2.z * alpha + E2.z; c2.w = c2.w * alpha + E2.w;              \
            c3.x = c3.x * alpha + E3.x; c3.y = c3.y * alpha + E3.y;              \
            c3.z = c3.z * alpha + E3.z; c3.w = c3.w * alpha + E3.w;              \
        } else {                                                                 \
            const float p = __expf(d - m);                                       \
            ssum += p;                                                           \
            c0.x = fmaf(p, E0.x, c0.x); c0.y = fmaf(p, E0.y, c0.y);              \
            c0.z = fmaf(p, E0.z, c0.z); c0.w = fmaf(p, E0.w, c0.w);              \
            c1.x = fmaf(p, E1.x, c1.x); c1.y = fmaf(p, E1.y, c1.y);              \
            c1.z = fmaf(p, E1.z, c1.z); c1.w = fmaf(p, E1.w, c1.w);              \
            c2.x = fmaf(p, E2.x, c2.x); c2.y = fmaf(p, E2.y, c2.y);              \
            c2.z = fmaf(p, E2.z, c2.z); c2.w = fmaf(p, E2.w, c2.w);              \
            c3.x = fmaf(p, E3.x, c3.x); c3.y = fmaf(p, E3.y, c3.y);              \
            c3.z = fmaf(p, E3.z, c3.z); c3.w = fmaf(p, E3.w, c3.w);              \
        }                                                                        \
    }

__global__ __launch_bounds__(256, 4) void k2_flash(const float* __restrict__ enc) {
    __shared__ __align__(16) float4 sbuf[K2_NSTAGE][8 * 128];   // 48 KB (static max)

    const int b = blockIdx.y;
    const int c = blockIdx.x;
    const int tid = threadIdx.x, w = tid >> 5, lane = tid & 31;

    const int L = g_len[b];                      // valid rows: t in [0, L)
    const int t0 = c * CHUNK;
    if (t0 >= L) {                               // entirely masked chunk
        if (tid == 0) g_ps[b * NCHUNK + c] = 0.f;
        return;
    }
    const int tend = min(t0 + CHUNK, L);
    const int total = (tend - t0 + 7) >> 3;      // stages for this block

    // v[b] from g_v (final; L2-hit loads, no reduce, no barriers)
    const float4* v4 = (const float4*)g_v + b * (HH / 4);
    const float4 va = v4[lane], vb = v4[lane + 32], vc = v4[lane + 64], vd = v4[lane + 96];

    const float4* ebase = (const float4*)enc + (size_t)b * TT * (HH / 4);

    // prefetch stages 0..2 (row t0 + st*8 + w; each thread stages what it reads)
#pragma unroll
    for (int st = 0; st < K2_NSTAGE; st++) {
        const int row = t0 + st * 8 + w;
        if (row < tend) {
            const float4* src = ebase + (size_t)row * 128;
#pragma unroll
            for (int k = 0; k < 4; k++)
                cpa16(&sbuf[st][w * 128 + lane + k * 32], src + lane + k * 32);
        }
        asm volatile("cp.async.commit_group;");
    }

    float m = -INFINITY, ssum = 0.f;
    float4 c0 = make_float4(0.f, 0.f, 0.f, 0.f), c1 = c0, c2 = c0, c3 = c0;

    for (int st = 0; st < total; st++) {
        asm volatile("cp.async.wait_group %0;" :: "n"(K2_NSTAGE - 1));
        const int buf = st % K2_NSTAGE;
        const int row = t0 + st * 8 + w;
        if (row < tend) {
            const float4 e0 = sbuf[buf][w * 128 + lane];
            const float4 e1 = sbuf[buf][w * 128 + lane + 32];
            const float4 e2 = sbuf[buf][w * 128 + lane + 64];
            const float4 e3 = sbuf[buf][w * 128 + lane + 96];
            PROCESS_ROW(e0, e1, e2, e3);
        }
        const int row2 = t0 + (st + K2_NSTAGE) * 8 + w;
        if (row2 < tend) {
            const float4* src = ebase + (size_t)row2 * 128;
#pragma unroll
            for (int k = 0; k < 4; k++)
                cpa16(&sbuf[buf][w * 128 + lane + k * 32], src + lane + k * 32);
        }
        asm volatile("cp.async.commit_group;");
    }
    asm volatile("cp.async.wait_group 0;");
    __syncthreads();                              // pipeline drained; reuse sbuf

    // ---- combine 8 warps: overlay sctx/sM/sS on sbuf ----
    float* sctx = (float*)sbuf;                   // [8][512] = 16 KB
    float* sMv  = (float*)sbuf + 8 * HH;          // 8 floats (start of sbuf[1])
    float* sSv  = sMv + 8;

    float4* sc4 = (float4*)(sctx + w * HH);
    sc4[lane] = c0; sc4[lane + 32] = c1; sc4[lane + 64] = c2; sc4[lane + 96] = c3;
    if (lane == 0) { sMv[w] = m; sSv[w] = ssum; }
    __syncthreads();

    float M = -INFINITY;
#pragma unroll
    for (int i = 0; i < 8; i++) if (sSv[i] > 0.f) M = fmaxf(M, sMv[i]);
    float S = 0.f, f[8];
#pragma unroll
    for (int i = 0; i < 8; i++) {
        f[i] = (sSv[i] > 0.f) ? __expf(sMv[i] - M) : 0.f;
        S += sSv[i] * f[i];
    }
    const int base = (b * NCHUNK + c) * HH;
    for (int h = tid; h < HH; h += 256) {
        float a = 0.f;
#pragma unroll
        for (int i = 0; i < 8; i++) a = fmaf(sctx[i * HH + h], f[i], a);
        g_pctx[base + h] = a;
    }
    if (tid == 0) { g_pm[b * NCHUNK + c] = M; g_ps[b * NCHUNK + c] = S; }
}

// ---------------------------------------------------------------------------
// Kernel 3: combine the NCHUNK split-softmax partials per batch.
// ---------------------------------------------------------------------------
__global__ void k3_combine(float* __restrict__ out) {
    const int b = blockIdx.x, h = threadIdx.x;   // 512 threads
    float M = -INFINITY;
#pragma unroll
    for (int c = 0; c < NCHUNK; c++) {
        const float s = g_ps[b * NCHUNK + c];
        if (s > 0.f) M = fmaxf(M, g_pm[b * NCHUNK + c]);
    }
    float S = 0.f, acc = 0.f;
#pragma unroll
    for (int c = 0; c < NCHUNK; c++) {
        const float s = g_ps[b * NCHUNK + c];
        if (s > 0.f) {
            const float fct = __expf(g_pm[b * NCHUNK + c] - M);
            S += s * fct;
            acc = fmaf(g_pctx[(b * NCHUNK + c) * HH + h], fct, acc);
        }
    }
    out[b * HH + h] = acc / S;
}

// ---------------------------------------------------------------------------
extern "C" void kernel_launch(void* const* d_in, const int* in_sizes, int n_in,
                              void* d_out, int out_size) {
    const float* query = nullptr;
    const float* enc   = nullptr;
    const float* W     = nullptr;
    const int*   tgt   = nullptr;   // dtype (i32 vs i64) detected on device
    for (int i = 0; i < n_in; i++) {
        switch (in_sizes[i]) {
            case BB * QQ:               query = (const float*)d_in[i]; break;
            case BB * TT * HH:          enc   = (const float*)d_in[i]; break;
            case QQ * HH:               W     = (const float*)d_in[i]; break;
            case BB:                    tgt   = (const int*)d_in[i]; break;
            default: break;             // bias (512) unused: softmax-shift invariant
        }
    }

    k1_proj<<<dim3(QSPLIT, BB / K1_BGRP), 256>>>(query, W);
    k1b_reduce<<<BB, 128>>>(tgt);
    k2_flash<<<dim3(NCHUNK, BB), 256>>>(enc);
    k3_combine<<<BB, HH>>>((float*)d_out);
}

// round 12
// speedup vs baseline: 1.1221x; 1.0615x over previous
#include <cuda_runtime.h>
#include <math.h>

#define BB 64
#define TT 2048
#define HH 512
#define QQ 512
#define NCHUNK 16
#define CHUNK (TT / NCHUNK)   // 128 rows per chunk
#define QSPLIT 16
#define QSEG (QQ / QSPLIT)    // 32

// Scratch (allocation-free rule: __device__ globals)
__device__ __align__(16) float g_vp[QSPLIT * BB * HH];   // partial v (2 MB)
__device__ __align__(16) float g_v[BB * HH];             // final v (128 KB)
__device__ int   g_len[BB];                              // valid length per batch
__device__ float g_pm[BB * NCHUNK];                      // per-chunk running max
__device__ float g_ps[BB * NCHUNK];                      // per-chunk exp-sum
__device__ __align__(16) float g_pctx[BB * NCHUNK * HH]; // per-chunk weighted ctx (2 MB)

__device__ __forceinline__ void cpa16(void* smem, const void* gmem) {
    unsigned s = (unsigned)__cvta_generic_to_shared(smem);
    asm volatile("cp.async.cg.shared.global [%0], [%1], 16;" :: "r"(s), "l"(gmem));
}
__device__ __forceinline__ void cpa4(void* smem, const void* gmem) {
    unsigned s = (unsigned)__cvta_generic_to_shared(smem);
    asm volatile("cp.async.ca.shared.global [%0], [%1], 4;" :: "r"(s), "l"(gmem));
}

// ---------------------------------------------------------------------------
// Kernel 1: K-split partial matvec (frozen: 6.6 us).
// grid (QSPLIT=16, 16) = 256 blocks, 256 threads (8 warps).
// ---------------------------------------------------------------------------
#define K1_BGRP   4
#define K1_ROWS   4
#define K1_NBUF   4
#define K1_STAGES (QSEG / K1_ROWS)   // 8

__global__ __launch_bounds__(256) void k1_proj(const float* __restrict__ query,
                                               const float* __restrict__ W) {
    const int qz = blockIdx.x;
    const int b0 = blockIdx.y * K1_BGRP;
    const int tid = threadIdx.x;
    const int h4 = tid & 127;
    const int bh = tid >> 7;              // 0: batches b0,b0+1  1: b0+2,b0+3

    __shared__ float sq[K1_BGRP][QSEG];                         // 0.5 KB
    __shared__ __align__(16) float4 sw[K1_NBUF][K1_ROWS * 128]; // 32 KB

    if (tid < K1_BGRP * QSEG)
        sq[tid >> 5][tid & 31] = query[(b0 + (tid >> 5)) * QQ + qz * QSEG + (tid & 31)];

    const float4* Wg = (const float4*)W + (size_t)qz * QSEG * (HH / 4);

#pragma unroll
    for (int s = 0; s < K1_NBUF - 1; s++) {
        cpa16(&sw[s][tid],       Wg + s * 512 + tid);
        cpa16(&sw[s][tid + 256], Wg + s * 512 + tid + 256);
        asm volatile("cp.async.commit_group;");
    }
    __syncthreads();                      // sq visible

    float4 a0 = make_float4(0.f, 0.f, 0.f, 0.f), a1 = a0;
    const int bq0 = 2 * bh, bq1 = 2 * bh + 1;

#pragma unroll
    for (int s = 0; s < K1_STAGES; s++) {
        asm volatile("cp.async.wait_group %0;" :: "n"(K1_NBUF - 2));
        __syncthreads();                  // staged stage-s data visible to all
        const int buf = s & (K1_NBUF - 1);
#pragma unroll
        for (int r = 0; r < K1_ROWS; r++) {
            const float4 w = sw[buf][r * 128 + h4];
            const int qi = s * K1_ROWS + r;
            const float q0 = sq[bq0][qi], q1 = sq[bq1][qi];
            a0.x = fmaf(w.x, q0, a0.x); a0.y = fmaf(w.y, q0, a0.y);
            a0.z = fmaf(w.z, q0, a0.z); a0.w = fmaf(w.w, q0, a0.w);
            a1.x = fmaf(w.x, q1, a1.x); a1.y = fmaf(w.y, q1, a1.y);
            a1.z = fmaf(w.z, q1, a1.z); a1.w = fmaf(w.w, q1, a1.w);
        }
        const int sn = s + K1_NBUF - 1;
        if (sn < K1_STAGES) {
            const int nb = sn & (K1_NBUF - 1);
            cpa16(&sw[nb][tid],       Wg + sn * 512 + tid);
            cpa16(&sw[nb][tid + 256], Wg + sn * 512 + tid + 256);
        }
        asm volatile("cp.async.commit_group;");
    }

    float4* vp = (float4*)g_vp + (size_t)qz * BB * (HH / 4);
    vp[(b0 + bq0) * (HH / 4) + h4] = a0;
    vp[(b0 + bq1) * (HH / 4) + h4] = a1;
}

// ---------------------------------------------------------------------------
// Kernel 1b: hoisted per-batch preamble (frozen). grid (BB=64), 128 threads.
// ---------------------------------------------------------------------------
__global__ __launch_bounds__(128) void k1b_reduce(const int* __restrict__ tgt_raw) {
    const int b = blockIdx.x;
    const int tid = threadIdx.x;          // h-float4 slot

    float4 a = make_float4(0.f, 0.f, 0.f, 0.f);
#pragma unroll
    for (int z = 0; z < QSPLIT; z++) {
        const float4 p = ((const float4*)g_vp)[((size_t)z * BB + b) * (HH / 4) + tid];
        a.x += p.x; a.y += p.y; a.z += p.z; a.w += p.w;
    }
    ((float4*)g_v)[b * (HH / 4) + tid] = a;

    if (tid == 0) {
        int odd_or = 0;
#pragma unroll
        for (int i = 1; i < 2 * BB; i += 2) odd_or |= tgt_raw[i];
        const int is64 = (odd_or == 0);
        g_len[b] = (is64 ? tgt_raw[2 * b] : tgt_raw[b]) + 1;
    }
}

// ---------------------------------------------------------------------------
// Kernel 2: flash pass, per-warp barrier-free cp.async pipeline (frozen).
// ---------------------------------------------------------------------------
#define K2_NSTAGE 3

__device__ __forceinline__ float dot4(float4 a, float4 b) {
    return a.x * b.x + a.y * b.y + a.z * b.z + a.w * b.w;
}

#define PROCESS_ROW(E0, E1, E2, E3)                                              \
    {                                                                            \
        float d = dot4(E0, va) + dot4(E1, vb) + dot4(E2, vc) + dot4(E3, vd);     \
        d += __shfl_xor_sync(0xFFFFFFFFu, d, 16);                                \
        d += __shfl_xor_sync(0xFFFFFFFFu, d, 8);                                 \
        d += __shfl_xor_sync(0xFFFFFFFFu, d, 4);                                 \
        d += __shfl_xor_sync(0xFFFFFFFFu, d, 2);                                 \
        d += __shfl_xor_sync(0xFFFFFFFFu, d, 1);                                 \
        if (d > m) {                                                             \
            const float alpha = __expf(m - d);                                   \
            m = d;                                                               \
            ssum = ssum * alpha + 1.f;                                           \
            c0.x = c0.x * alpha + E0.x; c0.y = c0.y * alpha + E0.y;              \
            c0.z = c0.z * alpha + E0.z; c0.w = c0.w * alpha + E0.w;              \
            c1.x = c1.x * alpha + E1.x; c1.y = c1.y * alpha + E1.y;              \
            c1.z = c1.z * alpha + E1.z; c1.w = c1.w * alpha + E1.w;              \
            c2.x = c2.x * alpha + E2.x; c2.y = c2.y * alpha + E2.y;              \
            c2.z = c2.z * alpha + E2.z; c2.w = c2.w * alpha + E2.w;              \
            c3.x = c3.x * alpha + E3.x; c3.y = c3.y * alpha + E3.y;              \
            c3.z = c3.z * alpha + E3.z; c3.w = c3.w * alpha + E3.w;              \
        } else {                                                                 \
            const float p = __expf(d - m);                                       \
            ssum += p;                                                           \
            c0.x = fmaf(p, E0.x, c0.x); c0.y = fmaf(p, E0.y, c0.y);              \
            c0.z = fmaf(p, E0.z, c0.z); c0.w = fmaf(p, E0.w, c0.w);              \
            c1.x = fmaf(p, E1.x, c1.x); c1.y = fmaf(p, E1.y, c1.y);              \
            c1.z = fmaf(p, E1.z, c1.z); c1.w = fmaf(p, E1.w, c1.w);              \
            c2.x = fmaf(p, E2.x, c2.x); c2.y = fmaf(p, E2.y, c2.y);              \
            c2.z = fmaf(p, E2.z, c2.z); c2.w = fmaf(p, E2.w, c2.w);              \
            c3.x = fmaf(p, E3.x, c3.x); c3.y = fmaf(p, E3.y, c3.y);              \
            c3.z = fmaf(p, E3.z, c3.z); c3.w = fmaf(p, E3.w, c3.w);              \
        }                                                                        \
    }

__global__ __launch_bounds__(256, 4) void k2_flash(const float* __restrict__ enc) {
    __shared__ __align__(16) float4 sbuf[K2_NSTAGE][8 * 128];   // 48 KB (static max)

    const int b = blockIdx.y;
    const int c = blockIdx.x;
    const int tid = threadIdx.x, w = tid >> 5, lane = tid & 31;

    const int L = g_len[b];                      // valid rows: t in [0, L)
    const int t0 = c * CHUNK;
    if (t0 >= L) {                               // entirely masked chunk
        if (tid == 0) g_ps[b * NCHUNK + c] = 0.f;
        return;
    }
    const int tend = min(t0 + CHUNK, L);
    const int total = (tend - t0 + 7) >> 3;      // stages for this block

    // v[b] from g_v (final; L2-hit loads, no reduce, no barriers)
    const float4* v4 = (const float4*)g_v + b * (HH / 4);
    const float4 va = v4[lane], vb = v4[lane + 32], vc = v4[lane + 64], vd = v4[lane + 96];

    const float4* ebase = (const float4*)enc + (size_t)b * TT * (HH / 4);

#pragma unroll
    for (int st = 0; st < K2_NSTAGE; st++) {
        const int row = t0 + st * 8 + w;
        if (row < tend) {
            const float4* src = ebase + (size_t)row * 128;
#pragma unroll
            for (int k = 0; k < 4; k++)
                cpa16(&sbuf[st][w * 128 + lane + k * 32], src + lane + k * 32);
        }
        asm volatile("cp.async.commit_group;");
    }

    float m = -INFINITY, ssum = 0.f;
    float4 c0 = make_float4(0.f, 0.f, 0.f, 0.f), c1 = c0, c2 = c0, c3 = c0;

    for (int st = 0; st < total; st++) {
        asm volatile("cp.async.wait_group %0;" :: "n"(K2_NSTAGE - 1));
        const int buf = st % K2_NSTAGE;
        const int row = t0 + st * 8 + w;
        if (row < tend) {
            const float4 e0 = sbuf[buf][w * 128 + lane];
            const float4 e1 = sbuf[buf][w * 128 + lane + 32];
            const float4 e2 = sbuf[buf][w * 128 + lane + 64];
            const float4 e3 = sbuf[buf][w * 128 + lane + 96];
            PROCESS_ROW(e0, e1, e2, e3);
        }
        const int row2 = t0 + (st + K2_NSTAGE) * 8 + w;
        if (row2 < tend) {
            const float4* src = ebase + (size_t)row2 * 128;
#pragma unroll
            for (int k = 0; k < 4; k++)
                cpa16(&sbuf[buf][w * 128 + lane + k * 32], src + lane + k * 32);
        }
        asm volatile("cp.async.commit_group;");
    }
    asm volatile("cp.async.wait_group 0;");
    __syncthreads();                              // pipeline drained; reuse sbuf

    // ---- combine 8 warps: overlay sctx/sM/sS on sbuf ----
    float* sctx = (float*)sbuf;                   // [8][512] = 16 KB
    float* sMv  = (float*)sbuf + 8 * HH;          // 8 floats (start of sbuf[1])
    float* sSv  = sMv + 8;

    float4* sc4 = (float4*)(sctx + w * HH);
    sc4[lane] = c0; sc4[lane + 32] = c1; sc4[lane + 64] = c2; sc4[lane + 96] = c3;
    if (lane == 0) { sMv[w] = m; sSv[w] = ssum; }
    __syncthreads();

    float M = -INFINITY;
#pragma unroll
    for (int i = 0; i < 8; i++) if (sSv[i] > 0.f) M = fmaxf(M, sMv[i]);
    float S = 0.f, f[8];
#pragma unroll
    for (int i = 0; i < 8; i++) {
        f[i] = (sSv[i] > 0.f) ? __expf(sMv[i] - M) : 0.f;
        S += sSv[i] * f[i];
    }
    const int base = (b * NCHUNK + c) * HH;
    for (int h = tid; h < HH; h += 256) {
        float a = 0.f;
#pragma unroll
        for (int i = 0; i < 8; i++) a = fmaf(sctx[i * HH + h], f[i], a);
        g_pctx[base + h] = a;
    }
    if (tid == 0) { g_pm[b * NCHUNK + c] = M; g_ps[b * NCHUNK + c] = S; }
}

// ---------------------------------------------------------------------------
// Kernel 3: combine the NCHUNK split-softmax partials per batch.
// grid (BB), 512 threads. cp.async-stages the full 32 KB pctx slab (L2-hit,
// guaranteed MLP) + pm/ps, then 16 smem FMAs per thread. No branch-guarded
// global loads.
// ---------------------------------------------------------------------------
__global__ __launch_bounds__(512) void k3_combine(float* __restrict__ out) {
    __shared__ __align__(16) float4 sp[NCHUNK * 128];   // 32 KB: pctx[b] slab
    __shared__ float spm[NCHUNK], sps[NCHUNK];

    const int b = blockIdx.x, tid = threadIdx.x;        // tid = h

    // stage pctx[b]: 2048 float4, 4 per thread (consecutive: coalesced L2 hits)
    const float4* src = (const float4*)g_pctx + (size_t)b * NCHUNK * (HH / 4);
#pragma unroll
    for (int i = 0; i < 4; i++)
        cpa16(&sp[tid + i * 512], src + tid + i * 512);
    if (tid < NCHUNK)      cpa4(&spm[tid], &g_pm[b * NCHUNK + tid]);
    else if (tid < 2 * NCHUNK) cpa4(&sps[tid - NCHUNK], &g_ps[b * NCHUNK + tid - NCHUNK]);
    asm volatile("cp.async.commit_group;");
    asm volatile("cp.async.wait_group 0;");
    __syncthreads();

    float M = -INFINITY;
#pragma unroll
    for (int c = 0; c < NCHUNK; c++)
        if (sps[c] > 0.f) M = fmaxf(M, spm[c]);

    float S = 0.f, acc = 0.f;
    const float* spf = (const float*)sp;
#pragma unroll
    for (int c = 0; c < NCHUNK; c++) {
        const float fct = (sps[c] > 0.f) ? __expf(spm[c] - M) : 0.f;
        S += sps[c] * fct;
        acc = fmaf(spf[c * HH + tid], fct, acc);   // masked: fct=0, value finite
    }
    out[b * HH + tid] = acc / S;
}

// ---------------------------------------------------------------------------
extern "C" void kernel_launch(void* const* d_in, const int* in_sizes, int n_in,
                              void* d_out, int out_size) {
    const float* query = nullptr;
    const float* enc   = nullptr;
    const float* W     = nullptr;
    const int*   tgt   = nullptr;   // dtype (i32 vs i64) detected on device
    for (int i = 0; i < n_in; i++) {
        switch (in_sizes[i]) {
            case BB * QQ:               query = (const float*)d_in[i]; break;
            case BB * TT * HH:          enc   = (const float*)d_in[i]; break;
            case QQ * HH:               W     = (const float*)d_in[i]; break;
            case BB:                    tgt   = (const int*)d_in[i]; break;
            default: break;             // bias (512) unused: softmax-shift invariant
        }
    }

    k1_proj<<<dim3(QSPLIT, BB / K1_BGRP), 256>>>(query, W);
    k1b_reduce<<<BB, 128>>>(tgt);
    k2_flash<<<dim3(NCHUNK, BB), 256>>>(enc);
    k3_combine<<<BB, 512>>>((float*)d_out);
}

// round 13
// speedup vs baseline: 1.1232x; 1.0010x over previous
#include <cuda_runtime.h>
#include <math.h>

#define BB 64
#define TT 2048
#define HH 512
#define QQ 512
#define NCHUNK 16
#define CHUNK (TT / NCHUNK)   // 128 rows per chunk
#define QSPLIT 16
#define QSEG (QQ / QSPLIT)    // 32

// Scratch (allocation-free rule: __device__ globals)
__device__ __align__(16) float g_vp[QSPLIT * BB * HH];   // partial v (2 MB)
__device__ __align__(16) float g_v[BB * HH];             // final v (128 KB)
__device__ int   g_len[BB];                              // valid length per batch
__device__ float g_pm[BB * NCHUNK];                      // per-chunk running max
__device__ float g_ps[BB * NCHUNK];                      // per-chunk exp-sum
__device__ __align__(16) float g_pctx[BB * NCHUNK * HH]; // per-chunk weighted ctx (2 MB)

__device__ __forceinline__ void cpa16(void* smem, const void* gmem) {
    unsigned s = (unsigned)__cvta_generic_to_shared(smem);
    asm volatile("cp.async.cg.shared.global [%0], [%1], 16;" :: "r"(s), "l"(gmem));
}
__device__ __forceinline__ void cpa4(void* smem, const void* gmem) {
    unsigned s = (unsigned)__cvta_generic_to_shared(smem);
    asm volatile("cp.async.ca.shared.global [%0], [%1], 4;" :: "r"(s), "l"(gmem));
}

// ---------------------------------------------------------------------------
// Kernel 1: K-split partial matvec (frozen: 6.6 us).
// grid (QSPLIT=16, 16) = 256 blocks, 256 threads (8 warps).
// ---------------------------------------------------------------------------
#define K1_BGRP   4
#define K1_ROWS   4
#define K1_NBUF   4
#define K1_STAGES (QSEG / K1_ROWS)   // 8

__global__ __launch_bounds__(256) void k1_proj(const float* __restrict__ query,
                                               const float* __restrict__ W) {
    const int qz = blockIdx.x;
    const int b0 = blockIdx.y * K1_BGRP;
    const int tid = threadIdx.x;
    const int h4 = tid & 127;
    const int bh = tid >> 7;              // 0: batches b0,b0+1  1: b0+2,b0+3

    __shared__ float sq[K1_BGRP][QSEG];                         // 0.5 KB
    __shared__ __align__(16) float4 sw[K1_NBUF][K1_ROWS * 128]; // 32 KB

    if (tid < K1_BGRP * QSEG)
        sq[tid >> 5][tid & 31] = query[(b0 + (tid >> 5)) * QQ + qz * QSEG + (tid & 31)];

    const float4* Wg = (const float4*)W + (size_t)qz * QSEG * (HH / 4);

#pragma unroll
    for (int s = 0; s < K1_NBUF - 1; s++) {
        cpa16(&sw[s][tid],       Wg + s * 512 + tid);
        cpa16(&sw[s][tid + 256], Wg + s * 512 + tid + 256);
        asm volatile("cp.async.commit_group;");
    }
    __syncthreads();                      // sq visible

    float4 a0 = make_float4(0.f, 0.f, 0.f, 0.f), a1 = a0;
    const int bq0 = 2 * bh, bq1 = 2 * bh + 1;

#pragma unroll
    for (int s = 0; s < K1_STAGES; s++) {
        asm volatile("cp.async.wait_group %0;" :: "n"(K1_NBUF - 2));
        __syncthreads();                  // staged stage-s data visible to all
        const int buf = s & (K1_NBUF - 1);
#pragma unroll
        for (int r = 0; r < K1_ROWS; r++) {
            const float4 w = sw[buf][r * 128 + h4];
            const int qi = s * K1_ROWS + r;
            const float q0 = sq[bq0][qi], q1 = sq[bq1][qi];
            a0.x = fmaf(w.x, q0, a0.x); a0.y = fmaf(w.y, q0, a0.y);
            a0.z = fmaf(w.z, q0, a0.z); a0.w = fmaf(w.w, q0, a0.w);
            a1.x = fmaf(w.x, q1, a1.x); a1.y = fmaf(w.y, q1, a1.y);
            a1.z = fmaf(w.z, q1, a1.z); a1.w = fmaf(w.w, q1, a1.w);
        }
        const int sn = s + K1_NBUF - 1;
        if (sn < K1_STAGES) {
            const int nb = sn & (K1_NBUF - 1);
            cpa16(&sw[nb][tid],       Wg + sn * 512 + tid);
            cpa16(&sw[nb][tid + 256], Wg + sn * 512 + tid + 256);
        }
        asm volatile("cp.async.commit_group;");
    }

    float4* vp = (float4*)g_vp + (size_t)qz * BB * (HH / 4);
    vp[(b0 + bq0) * (HH / 4) + h4] = a0;
    vp[(b0 + bq1) * (HH / 4) + h4] = a1;
}

// ---------------------------------------------------------------------------
// Kernel 1b: hoisted per-batch preamble (frozen). grid (BB=64), 128 threads.
// ---------------------------------------------------------------------------
__global__ __launch_bounds__(128) void k1b_reduce(const int* __restrict__ tgt_raw) {
    const int b = blockIdx.x;
    const int tid = threadIdx.x;          // h-float4 slot

    float4 a = make_float4(0.f, 0.f, 0.f, 0.f);
#pragma unroll
    for (int z = 0; z < QSPLIT; z++) {
        const float4 p = ((const float4*)g_vp)[((size_t)z * BB + b) * (HH / 4) + tid];
        a.x += p.x; a.y += p.y; a.z += p.z; a.w += p.w;
    }
    ((float4*)g_v)[b * (HH / 4) + tid] = a;

    if (tid == 0) {
        int odd_or = 0;
#pragma unroll
        for (int i = 1; i < 2 * BB; i += 2) odd_or |= tgt_raw[i];
        const int is64 = (odd_or == 0);
        g_len[b] = (is64 ? tgt_raw[2 * b] : tgt_raw[b]) + 1;
    }
}

// ---------------------------------------------------------------------------
// Kernel 2: flash pass, per-warp barrier-free cp.async pipeline (frozen).
// ---------------------------------------------------------------------------
#define K2_NSTAGE 3

__device__ __forceinline__ float dot4(float4 a, float4 b) {
    return a.x * b.x + a.y * b.y + a.z * b.z + a.w * b.w;
}

#define PROCESS_ROW(E0, E1, E2, E3)                                              \
    {                                                                            \
        float d = dot4(E0, va) + dot4(E1, vb) + dot4(E2, vc) + dot4(E3, vd);     \
        d += __shfl_xor_sync(0xFFFFFFFFu, d, 16);                                \
        d += __shfl_xor_sync(0xFFFFFFFFu, d, 8);                                 \
        d += __shfl_xor_sync(0xFFFFFFFFu, d, 4);                                 \
        d += __shfl_xor_sync(0xFFFFFFFFu, d, 2);                                 \
        d += __shfl_xor_sync(0xFFFFFFFFu, d, 1);                                 \
        if (d > m) {                                                             \
            const float alpha = __expf(m - d);                                   \
            m = d;                                                               \
            ssum = ssum * alpha + 1.f;                                           \
            c0.x = c0.x * alpha + E0.x; c0.y = c0.y * alpha + E0.y;              \
            c0.z = c0.z * alpha + E0.z; c0.w = c0.w * alpha + E0.w;              \
            c1.x = c1.x * alpha + E1.x; c1.y = c1.y * alpha + E1.y;              \
            c1.z = c1.z * alpha + E1.z; c1.w = c1.w * alpha + E1.w;              \
            c2.x = c2.x * alpha + E2.x; c2.y = c2.y * alpha + E2.y;              \
            c2.z = c2.z * alpha + E2.z; c2.w = c2.w * alpha + E2.w;              \
            c3.x = c3.x * alpha + E3.x; c3.y = c3.y * alpha + E3.y;              \
            c3.z = c3.z * alpha + E3.z; c3.w = c3.w * alpha + E3.w;              \
        } else {                                                                 \
            const float p = __expf(d - m);                                       \
            ssum += p;                                                           \
            c0.x = fmaf(p, E0.x, c0.x); c0.y = fmaf(p, E0.y, c0.y);              \
            c0.z = fmaf(p, E0.z, c0.z); c0.w = fmaf(p, E0.w, c0.w);              \
            c1.x = fmaf(p, E1.x, c1.x); c1.y = fmaf(p, E1.y, c1.y);              \
            c1.z = fmaf(p, E1.z, c1.z); c1.w = fmaf(p, E1.w, c1.w);              \
            c2.x = fmaf(p, E2.x, c2.x); c2.y = fmaf(p, E2.y, c2.y);              \
            c2.z = fmaf(p, E2.z, c2.z); c2.w = fmaf(p, E2.w, c2.w);              \
            c3.x = fmaf(p, E3.x, c3.x); c3.y = fmaf(p, E3.y, c3.y);              \
            c3.z = fmaf(p, E3.z, c3.z); c3.w = fmaf(p, E3.w, c3.w);              \
        }                                                                        \
    }

__global__ __launch_bounds__(256, 4) void k2_flash(const float* __restrict__ enc) {
    __shared__ __align__(16) float4 sbuf[K2_NSTAGE][8 * 128];   // 48 KB (static max)

    const int b = blockIdx.y;
    const int c = blockIdx.x;
    const int tid = threadIdx.x, w = tid >> 5, lane = tid & 31;

    const int L = g_len[b];                      // valid rows: t in [0, L)
    const int t0 = c * CHUNK;
    if (t0 >= L) {                               // entirely masked chunk
        if (tid == 0) g_ps[b * NCHUNK + c] = 0.f;
        return;
    }
    const int tend = min(t0 + CHUNK, L);
    const int total = (tend - t0 + 7) >> 3;      // stages for this block

    // v[b] from g_v (final; L2-hit loads, no reduce, no barriers)
    const float4* v4 = (const float4*)g_v + b * (HH / 4);
    const float4 va = v4[lane], vb = v4[lane + 32], vc = v4[lane + 64], vd = v4[lane + 96];

    const float4* ebase = (const float4*)enc + (size_t)b * TT * (HH / 4);

#pragma unroll
    for (int st = 0; st < K2_NSTAGE; st++) {
        const int row = t0 + st * 8 + w;
        if (row < tend) {
            const float4* src = ebase + (size_t)row * 128;
#pragma unroll
            for (int k = 0; k < 4; k++)
                cpa16(&sbuf[st][w * 128 + lane + k * 32], src + lane + k * 32);
        }
        asm volatile("cp.async.commit_group;");
    }

    float m = -INFINITY, ssum = 0.f;
    float4 c0 = make_float4(0.f, 0.f, 0.f, 0.f), c1 = c0, c2 = c0, c3 = c0;

    for (int st = 0; st < total; st++) {
        asm volatile("cp.async.wait_group %0;" :: "n"(K2_NSTAGE - 1));
        const int buf = st % K2_NSTAGE;
        const int row = t0 + st * 8 + w;
        if (row < tend) {
            const float4 e0 = sbuf[buf][w * 128 + lane];
            const float4 e1 = sbuf[buf][w * 128 + lane + 32];
            const float4 e2 = sbuf[buf][w * 128 + lane + 64];
            const float4 e3 = sbuf[buf][w * 128 + lane + 96];
            PROCESS_ROW(e0, e1, e2, e3);
        }
        const int row2 = t0 + (st + K2_NSTAGE) * 8 + w;
        if (row2 < tend) {
            const float4* src = ebase + (size_t)row2 * 128;
#pragma unroll
            for (int k = 0; k < 4; k++)
                cpa16(&sbuf[buf][w * 128 + lane + k * 32], src + lane + k * 32);
        }
        asm volatile("cp.async.commit_group;");
    }
    asm volatile("cp.async.wait_group 0;");
    __syncthreads();                              // pipeline drained; reuse sbuf

    // ---- combine 8 warps: overlay sctx/sM/sS on sbuf ----
    float* sctx = (float*)sbuf;                   // [8][512] = 16 KB
    float* sMv  = (float*)sbuf + 8 * HH;          // 8 floats (start of sbuf[1])
    float* sSv  = sMv + 8;

    float4* sc4 = (float4*)(sctx + w * HH);
    sc4[lane] = c0; sc4[lane + 32] = c1; sc4[lane + 64] = c2; sc4[lane + 96] = c3;
    if (lane == 0) { sMv[w] = m; sSv[w] = ssum; }
    __syncthreads();

    float M = -INFINITY;
#pragma unroll
    for (int i = 0; i < 8; i++) if (sSv[i] > 0.f) M = fmaxf(M, sMv[i]);
    float S = 0.f, f[8];
#pragma unroll
    for (int i = 0; i < 8; i++) {
        f[i] = (sSv[i] > 0.f) ? __expf(sMv[i] - M) : 0.f;
        S += sSv[i] * f[i];
    }
    const int base = (b * NCHUNK + c) * HH;
    for (int h = tid; h < HH; h += 256) {
        float a = 0.f;
#pragma unroll
        for (int i = 0; i < 8; i++) a = fmaf(sctx[i * HH + h], f[i], a);
        g_pctx[base + h] = a;
    }
    if (tid == 0) { g_pm[b * NCHUNK + c] = M; g_ps[b * NCHUNK + c] = S; }
}

// ---------------------------------------------------------------------------
// Kernel 3: combine partials. grid (BB, 4) = 256 blocks, 128 threads.
// Block (b, hs) handles h in [hs*128, hs*128+128). Warp w stages chunks
// {w, w+4, w+8, w+12} of the pctx slice via cp.async (8 KB), then 16 smem
// FMAs per thread. 4x the blocks of the R12 version -> latency amortized.
// ---------------------------------------------------------------------------
__global__ __launch_bounds__(128) void k3_combine(float* __restrict__ out) {
    __shared__ __align__(16) float4 sp[NCHUNK * 32];    // 8 KB: pctx slice
    __shared__ float spm[NCHUNK], sps[NCHUNK];

    const int b = blockIdx.x, hs = blockIdx.y;
    const int tid = threadIdx.x, w = tid >> 5, lane = tid & 31;

    const float4* src = (const float4*)g_pctx + (size_t)b * NCHUNK * (HH / 4) + hs * 32;
#pragma unroll
    for (int i = 0; i < 4; i++) {
        const int c = i * 4 + w;
        cpa16(&sp[c * 32 + lane], src + (size_t)c * (HH / 4) + lane);
    }
    if (tid < NCHUNK)          cpa4(&spm[tid], &g_pm[b * NCHUNK + tid]);
    else if (tid < 2 * NCHUNK) cpa4(&sps[tid - NCHUNK], &g_ps[b * NCHUNK + tid - NCHUNK]);
    asm volatile("cp.async.commit_group;");
    asm volatile("cp.async.wait_group 0;");
    __syncthreads();

    float M = -INFINITY;
#pragma unroll
    for (int c = 0; c < NCHUNK; c++)
        if (sps[c] > 0.f) M = fmaxf(M, spm[c]);

    float S = 0.f, acc = 0.f;
    const float* spf = (const float*)sp;
#pragma unroll
    for (int c = 0; c < NCHUNK; c++) {
        const float fct = (sps[c] > 0.f) ? __expf(spm[c] - M) : 0.f;
        S += sps[c] * fct;
        acc = fmaf(spf[c * 128 + tid], fct, acc);  // masked: fct=0, value finite
    }
    out[b * HH + hs * 128 + tid] = acc / S;
}

// ---------------------------------------------------------------------------
extern "C" void kernel_launch(void* const* d_in, const int* in_sizes, int n_in,
                              void* d_out, int out_size) {
    const float* query = nullptr;
    const float* enc   = nullptr;
    const float* W     = nullptr;
    const int*   tgt   = nullptr;   // dtype (i32 vs i64) detected on device
    for (int i = 0; i < n_in; i++) {
        switch (in_sizes[i]) {
            case BB * QQ:               query = (const float*)d_in[i]; break;
            case BB * TT * HH:          enc   = (const float*)d_in[i]; break;
            case QQ * HH:               W     = (const float*)d_in[i]; break;
            case BB:                    tgt   = (const int*)d_in[i]; break;
            default: break;             // bias (512) unused: softmax-shift invariant
        }
    }

    k1_proj<<<dim3(QSPLIT, BB / K1_BGRP), 256>>>(query, W);
    k1b_reduce<<<BB, 128>>>(tgt);
    k2_flash<<<dim3(NCHUNK, BB), 256>>>(enc);
    k3_combine<<<dim3(BB, 4), 128>>>((float*)d_out);
}